// round 15
// baseline (speedup 1.0000x reference)
#include <cuda_runtime.h>
#include <cuda_fp16.h>
#include <cstdint>

#define DIM 512
#define HEADS 8
#define DHEAD 64
#define BATCH 4
#define NSEQ 2048
#define ROWS (BATCH * NSEQ)   // 8192

// ================= scratch (no allocations allowed) =================
__device__ __half g_xnh[ROWS * DIM];
__device__ __half g_qh[ROWS * DIM];
__device__ __half g_kh[ROWS * DIM];
__device__ __half g_vh[ROWS * DIM];
__device__ __half g_ath[ROWS * DIM];
__device__ __half g_wqh[DIM * DIM];
__device__ __half g_wkh[DIM * DIM];
__device__ __half g_wvh[DIM * DIM];
__device__ __half g_woh[DIM * DIM], g_wol[DIM * DIM];

// ================= helpers =================
__device__ __forceinline__ uint32_t smem_u32(const void* p) {
    uint32_t a;
    asm("{ .reg .u64 t; cvta.to.shared.u64 t, %1; cvt.u32.u64 %0, t; }" : "=r"(a) : "l"(p));
    return a;
}
__device__ __forceinline__ void ldsm4(uint32_t* r, uint32_t a) {
    asm volatile("ldmatrix.sync.aligned.m8n8.x4.shared.b16 {%0,%1,%2,%3}, [%4];"
                 : "=r"(r[0]), "=r"(r[1]), "=r"(r[2]), "=r"(r[3]) : "r"(a));
}
__device__ __forceinline__ void ldsm4t(uint32_t* r, uint32_t a) {
    asm volatile("ldmatrix.sync.aligned.m8n8.x4.trans.shared.b16 {%0,%1,%2,%3}, [%4];"
                 : "=r"(r[0]), "=r"(r[1]), "=r"(r[2]), "=r"(r[3]) : "r"(a));
}
__device__ __forceinline__ void mmaf32(float* c, const uint32_t* a, const uint32_t* b) {
    asm volatile("mma.sync.aligned.m16n8k16.row.col.f32.f16.f16.f32 "
                 "{%0,%1,%2,%3}, {%4,%5,%6,%7}, {%8,%9}, {%0,%1,%2,%3};"
                 : "+f"(c[0]), "+f"(c[1]), "+f"(c[2]), "+f"(c[3])
                 : "r"(a[0]), "r"(a[1]), "r"(a[2]), "r"(a[3]), "r"(b[0]), "r"(b[1]));
}
__device__ __forceinline__ void cpa16(uint32_t d, const void* s) {
    asm volatile("cp.async.cg.shared.global [%0], [%1], 16;" :: "r"(d), "l"(s));
}
#define CP_COMMIT() asm volatile("cp.async.commit_group;")
#define CP_WAIT(n)  asm volatile("cp.async.wait_group %0;" :: "n"(n))

__device__ __forceinline__ uint32_t h2pack(float a, float b) {
    __half2 t = __floats2half2_rn(a, b);
    return *reinterpret_cast<uint32_t*>(&t);
}
__device__ __forceinline__ float hres(float a) {
    __half h = __float2half_rn(a);
    return a - __half2float(h);
}

// ================= fused prep: ln (blocks 0..8191) + conv3 (8192..9215) + wnorm (9216..9727) =================
__global__ __launch_bounds__(256) void prep_kernel(const float* __restrict__ x,
                                                   const float* __restrict__ w,
                                                   const float* __restrict__ b,
                                                   const float* __restrict__ wq,
                                                   const float* __restrict__ wk,
                                                   const float* __restrict__ wo,
                                                   const float* __restrict__ wv_v,
                                                   const float* __restrict__ wv_g) {
    int t = threadIdx.x;
    if (blockIdx.x < ROWS) {
        __shared__ float sb1[8], sb2[8];
        int row = blockIdx.x;
        const float* xr = x + (size_t)row * DIM;
        float v0 = xr[t], v1 = xr[t + 256];
        float s = v0 + v1, ss = v0 * v0 + v1 * v1;
        #pragma unroll
        for (int o = 16; o > 0; o >>= 1) {
            s  += __shfl_xor_sync(~0u, s, o);
            ss += __shfl_xor_sync(~0u, ss, o);
        }
        int lane = t & 31, wd = t >> 5;
        if (lane == 0) { sb1[wd] = s; sb2[wd] = ss; }
        __syncthreads();
        if (wd == 0) {
            float r1 = (lane < 8) ? sb1[lane] : 0.f, r2 = (lane < 8) ? sb2[lane] : 0.f;
            #pragma unroll
            for (int o = 4; o > 0; o >>= 1) {
                r1 += __shfl_xor_sync(~0u, r1, o);
                r2 += __shfl_xor_sync(~0u, r2, o);
            }
            if (lane == 0) { sb1[0] = r1; sb2[0] = r2; }
        }
        __syncthreads();
        float mu  = sb1[0] * (1.f / DIM);
        float var = sb2[0] * (1.f / DIM) - mu * mu;
        float inv = rsqrtf(var + 1e-5f);
        size_t base = (size_t)row * DIM;
        g_xnh[base + t]       = __float2half_rn((v0 - mu) * inv * w[t] + b[t]);
        g_xnh[base + t + 256] = __float2half_rn((v1 - mu) * inv * w[t + 256] + b[t + 256]);
    } else if (blockIdx.x < ROWS + DIM * DIM / 256) {
        int i = (blockIdx.x - ROWS) * 256 + t;
        g_wqh[i] = __float2half_rn(wq[i]);
        g_wkh[i] = __float2half_rn(wk[i]);
        float f2 = wo[i];
        g_woh[i] = __float2half_rn(f2);
        g_wol[i] = __float2half_rn(hres(f2));
    } else {
        __shared__ float sbuf[8];
        int row = blockIdx.x - (ROWS + DIM * DIM / 256);
        const float* vr = wv_v + (size_t)row * DIM;
        float v0 = vr[t], v1 = vr[t + 256];
        float ss = v0 * v0 + v1 * v1;
        #pragma unroll
        for (int o = 16; o > 0; o >>= 1) ss += __shfl_xor_sync(~0u, ss, o);
        int lane = t & 31, wd = t >> 5;
        if (lane == 0) sbuf[wd] = ss;
        __syncthreads();
        if (wd == 0) {
            float r = (lane < 8) ? sbuf[lane] : 0.f;
            #pragma unroll
            for (int o = 4; o > 0; o >>= 1) r += __shfl_xor_sync(~0u, r, o);
            if (lane == 0) sbuf[0] = r;
        }
        __syncthreads();
        float sc = wv_g[row] * rsqrtf(sbuf[0]);
        size_t base = (size_t)row * DIM;
        g_wvh[base + t]       = __float2half_rn(v0 * sc);
        g_wvh[base + t + 256] = __float2half_rn(v1 * sc);
    }
}

#define GP 144
#define TT (128 * GP)          // 18432 per tile

// ================= 1-term fp16 QKV GEMM: one CTA does z=0,1,2 serially =================
#define ST1 (2 * TT)           // 36864 per stage
#define G1_SMEM (2 * ST1)      // 73728

__global__ __launch_bounds__(256, 2)
void gemm1(const __half* __restrict__ Ah,
           const __half* __restrict__ B0, __half* __restrict__ C0, float s0,
           const __half* __restrict__ B1, __half* __restrict__ C1, float s1,
           const __half* __restrict__ B2, __half* __restrict__ C2, float s2) {
    extern __shared__ char sm[];
    uint32_t sb = smem_u32(sm);
    int tid = threadIdx.x, lane = tid & 31, wd = tid >> 5;
    int wm = wd & 3, wn = wd >> 2;
    int tm = blockIdx.y * 128, tn = blockIdx.x * 128;

    #pragma unroll 1
    for (int z = 0; z < 3; z++) {
        const __half* Bh = z == 0 ? B0 : (z == 1 ? B1 : B2);
        __half* Ch = z == 0 ? C0 : (z == 1 ? C1 : C2);
        float scale = z == 0 ? s0 : (z == 1 ? s1 : s2);

        float c[2][8][4];
        #pragma unroll
        for (int i = 0; i < 2; i++)
            #pragma unroll
            for (int j = 0; j < 8; j++)
                #pragma unroll
                for (int e = 0; e < 4; e++) c[i][j][e] = 0.f;

        auto stage = [&](int kc, uint32_t buf) {
            int k0 = kc * 64;
            #pragma unroll
            for (int u = 0; u < 4; u++) {
                int e = tid + u * 256;
                int r = e >> 3, c8 = (e & 7) * 8;
                uint32_t d = buf + (uint32_t)r * GP + c8 * 2;
                cpa16(d, &Ah[(size_t)(tm + r) * DIM + k0 + c8]);
                cpa16(d + TT, &Bh[(size_t)(tn + r) * DIM + k0 + c8]);
            }
        };

        stage(0, sb);
        CP_COMMIT();

        for (int kc = 0; kc < 8; kc++) {
            CP_WAIT(0);
            __syncthreads();
            if (kc < 7) {
                stage(kc + 1, sb + ((kc + 1) & 1) * ST1);
                CP_COMMIT();
            }
            uint32_t buf = sb + (kc & 1) * ST1;
            #pragma unroll
            for (int ks = 0; ks < 4; ks++) {
                uint32_t ah[2][4];
                uint32_t acol = ks * 32 + ((lane >> 4) << 4);
                #pragma unroll
                for (int mt = 0; mt < 2; mt++) {
                    uint32_t arow = wm * 32 + mt * 16 + (lane & 15);
                    ldsm4(ah[mt], buf + arow * GP + acol);
                }
                uint32_t bro = ((lane >> 4) << 3) + (lane & 7);
                uint32_t bcol = ks * 32 + (((lane >> 3) & 1) << 4);
                #pragma unroll
                for (int p = 0; p < 4; p++) {
                    uint32_t nrow = wn * 64 + p * 16 + bro;
                    uint32_t bh[4];
                    ldsm4(bh, buf + TT + nrow * GP + bcol);
                    #pragma unroll
                    for (int mt = 0; mt < 2; mt++) {
                        mmaf32(c[mt][2 * p],     ah[mt], &bh[0]);
                        mmaf32(c[mt][2 * p + 1], ah[mt], &bh[2]);
                    }
                }
            }
            __syncthreads();
        }

        int g = lane >> 2, t4 = lane & 3;
        #pragma unroll
        for (int mt = 0; mt < 2; mt++) {
            #pragma unroll
            for (int nt = 0; nt < 8; nt++) {
                int row = tm + wm * 32 + mt * 16 + g;
                int col = tn + wn * 64 + nt * 8 + t4 * 2;
                *(uint32_t*)&Ch[(size_t)row * DIM + col] =
                    h2pack(c[mt][nt][0] * scale, c[mt][nt][1] * scale);
                *(uint32_t*)&Ch[(size_t)(row + 8) * DIM + col] =
                    h2pack(c[mt][nt][2] * scale, c[mt][nt][3] * scale);
            }
        }
    }
}

// ================= 2-term output GEMM: C_f = A_h * (B_h + B_l)^T, occ 2 =================
#define STO (3 * TT)           // 55296 per stage
#define GO_SMEM (2 * STO)      // 110592

__global__ __launch_bounds__(256, 2)
void gemmO(const __half* __restrict__ Ah,
           const __half* __restrict__ Bh, const __half* __restrict__ Bl,
           float* __restrict__ Cf) {
    extern __shared__ char sm[];
    uint32_t sb = smem_u32(sm);
    int tid = threadIdx.x, lane = tid & 31, wd = tid >> 5;
    int wm = wd & 3, wn = wd >> 2;
    int tm = blockIdx.y * 128, tn = blockIdx.x * 128;

    float c[2][8][4];
    #pragma unroll
    for (int i = 0; i < 2; i++)
        #pragma unroll
        for (int j = 0; j < 8; j++)
            #pragma unroll
            for (int e = 0; e < 4; e++) c[i][j][e] = 0.f;

    auto stage = [&](int kc, uint32_t buf) {
        int k0 = kc * 64;
        #pragma unroll
        for (int u = 0; u < 4; u++) {
            int e = tid + u * 256;
            int r = e >> 3, c8 = (e & 7) * 8;
            uint32_t d = buf + (uint32_t)r * GP + c8 * 2;
            cpa16(d, &Ah[(size_t)(tm + r) * DIM + k0 + c8]);
            cpa16(d + TT, &Bh[(size_t)(tn + r) * DIM + k0 + c8]);
            cpa16(d + 2 * TT, &Bl[(size_t)(tn + r) * DIM + k0 + c8]);
        }
    };

    stage(0, sb);
    CP_COMMIT();

    for (int kc = 0; kc < 8; kc++) {
        CP_WAIT(0);
        __syncthreads();
        if (kc < 7) {
            stage(kc + 1, sb + ((kc + 1) & 1) * STO);
            CP_COMMIT();
        }
        uint32_t buf = sb + (kc & 1) * STO;
        #pragma unroll
        for (int ks = 0; ks < 4; ks++) {
            uint32_t ah[2][4];
            uint32_t acol = ks * 32 + ((lane >> 4) << 4);
            #pragma unroll
            for (int mt = 0; mt < 2; mt++) {
                uint32_t arow = wm * 32 + mt * 16 + (lane & 15);
                ldsm4(ah[mt], buf + arow * GP + acol);
            }
            uint32_t bro = ((lane >> 4) << 3) + (lane & 7);
            uint32_t bcol = ks * 32 + (((lane >> 3) & 1) << 4);
            #pragma unroll
            for (int p = 0; p < 4; p++) {
                uint32_t nrow = wn * 64 + p * 16 + bro;
                uint32_t bh[4], bl[4];
                ldsm4(bh, buf + TT + nrow * GP + bcol);
                ldsm4(bl, buf + 2 * TT + nrow * GP + bcol);
                #pragma unroll
                for (int mt = 0; mt < 2; mt++) {
                    mmaf32(c[mt][2 * p],     ah[mt], &bh[0]);
                    mmaf32(c[mt][2 * p],     ah[mt], &bl[0]);
                    mmaf32(c[mt][2 * p + 1], ah[mt], &bh[2]);
                    mmaf32(c[mt][2 * p + 1], ah[mt], &bl[2]);
                }
            }
        }
        __syncthreads();
    }

    int g = lane >> 2, t4 = lane & 3;
    #pragma unroll
    for (int mt = 0; mt < 2; mt++) {
        #pragma unroll
        for (int nt = 0; nt < 8; nt++) {
            int row = tm + wm * 32 + mt * 16 + g;
            int col = tn + wn * 64 + nt * 8 + t4 * 2;
            *(float2*)&Cf[(size_t)row * DIM + col] =
                make_float2(c[mt][nt][0], c[mt][nt][1]);
            *(float2*)&Cf[(size_t)(row + 8) * DIM + col] =
                make_float2(c[mt][nt][2], c[mt][nt][3]);
        }
    }
}

// ================= flash attention: 1-term fp16, exp2, occ 2, 2 i-tiles/CTA =================
#define AST (64 * GP)           // 9216 per tile
#define A_SMEM (2 * 2 * AST)    // 36864

__global__ __launch_bounds__(256, 2)
void attn_mma(const __half* __restrict__ Qh,
              const __half* __restrict__ Kh,
              const __half* __restrict__ Vh,
              __half* __restrict__ Oh) {
    extern __shared__ char sm[];
    uint32_t sb = smem_u32(sm);
    int tid = threadIdx.x, lane = tid & 31, wd = tid >> 5;
    int b = blockIdx.x >> 3, h = blockIdx.x & 7;
    size_t base = (size_t)b * NSEQ * DIM + (size_t)h * DHEAD;

    auto stage_kv = [&](int blk, uint32_t buf) {
        int j0 = blk * 64;
        #pragma unroll
        for (int u = 0; u < 2; u++) {
            int e = tid + u * 256;
            int r = e >> 3, c8 = (e & 7) * 8;
            uint32_t d = buf + (uint32_t)r * GP + c8 * 2;
            size_t ga = base + (size_t)(j0 + r) * DIM + c8;
            cpa16(d, &Kh[ga]);
            cpa16(d + AST, &Vh[ga]);
        }
    };

    #pragma unroll 1
    for (int it = 0; it < 2; it++) {
        int iBase = (blockIdx.y * 2 + it) * 128;

        // ---- stage Q hi ----
        #pragma unroll
        for (int u = 0; u < 4; u++) {
            int e = tid + u * 256;
            int r = e >> 3, c8 = (e & 7) * 8;
            uint32_t d = sb + (uint32_t)r * GP + c8 * 2;
            cpa16(d, &Qh[base + (size_t)(iBase + r) * DIM + c8]);
        }
        CP_COMMIT(); CP_WAIT(0);
        __syncthreads();

        uint32_t qh[4][4];
        {
            uint32_t arow = wd * 16 + (lane & 15);
            #pragma unroll
            for (int ks = 0; ks < 4; ks++) {
                uint32_t acol = ks * 32 + ((lane >> 4) << 4);
                ldsm4(qh[ks], sb + arow * GP + acol);
            }
        }
        __syncthreads();

        float o[8][4];
        #pragma unroll
        for (int i = 0; i < 8; i++)
            #pragma unroll
            for (int e = 0; e < 4; e++) o[i][e] = 0.f;
        float l0 = 0.f, l1 = 0.f;

        stage_kv(0, sb);
        CP_COMMIT();

        for (int bi = 0; bi < 32; bi++) {
            CP_WAIT(0);
            __syncthreads();
            uint32_t buf = sb + (bi & 1) * 2 * AST;
            if (bi < 31) {
                stage_kv(bi + 1, sb + ((bi + 1) & 1) * 2 * AST);
                CP_COMMIT();
            }

            float s[8][4];
            #pragma unroll
            for (int nt = 0; nt < 8; nt++)
                #pragma unroll
                for (int e = 0; e < 4; e++) s[nt][e] = 0.f;

            uint32_t bro = ((lane >> 4) << 3) + (lane & 7);
            #pragma unroll
            for (int ks = 0; ks < 4; ks++) {
                uint32_t bcol = ks * 32 + (((lane >> 3) & 1) << 4);
                #pragma unroll
                for (int p = 0; p < 4; p++) {
                    uint32_t nrow = p * 16 + bro;
                    uint32_t bh[4];
                    ldsm4(bh, buf + nrow * GP + bcol);
                    mmaf32(s[2 * p],     qh[ks], &bh[0]);
                    mmaf32(s[2 * p + 1], qh[ks], &bh[2]);
                }
            }

            #pragma unroll
            for (int nt = 0; nt < 8; nt++) {
                s[nt][0] = exp2f(s[nt][0]);
                s[nt][1] = exp2f(s[nt][1]);
                s[nt][2] = exp2f(s[nt][2]);
                s[nt][3] = exp2f(s[nt][3]);
                l0 += s[nt][0] + s[nt][1];
                l1 += s[nt][2] + s[nt][3];
            }

            uint32_t vro = (((lane >> 3) & 1) << 3) + (lane & 7);
            uint32_t vco = (lane >> 4) << 4;
            #pragma unroll
            for (int st = 0; st < 4; st++) {
                uint32_t a_h[4];
                a_h[0] = h2pack(s[2 * st][0], s[2 * st][1]);
                a_h[1] = h2pack(s[2 * st][2], s[2 * st][3]);
                a_h[2] = h2pack(s[2 * st + 1][0], s[2 * st + 1][1]);
                a_h[3] = h2pack(s[2 * st + 1][2], s[2 * st + 1][3]);
                uint32_t jrow = st * 16 + vro;
                #pragma unroll
                for (int dp = 0; dp < 4; dp++) {
                    uint32_t db = dp * 32 + vco;
                    uint32_t vh[4];
                    ldsm4t(vh, buf + AST + jrow * GP + db);
                    mmaf32(o[2 * dp],     a_h, &vh[0]);
                    mmaf32(o[2 * dp + 1], a_h, &vh[2]);
                }
            }
            __syncthreads();
        }

        l0 += __shfl_xor_sync(~0u, l0, 1); l0 += __shfl_xor_sync(~0u, l0, 2);
        l1 += __shfl_xor_sync(~0u, l1, 1); l1 += __shfl_xor_sync(~0u, l1, 2);
        float i0v = 1.f / l0, i1v = 1.f / l1;

        int g = lane >> 2, t4 = lane & 3;
        size_t ga0 = base + (size_t)(iBase + wd * 16 + g) * DIM + t4 * 2;
        size_t ga1 = ga0 + 8 * DIM;
        #pragma unroll
        for (int dt = 0; dt < 8; dt++) {
            *(uint32_t*)&Oh[ga0 + dt * 8] = h2pack(o[dt][0] * i0v, o[dt][1] * i0v);
            *(uint32_t*)&Oh[ga1 + dt * 8] = h2pack(o[dt][2] * i1v, o[dt][3] * i1v);
        }
    }
}

// ================= launch =================
extern "C" void kernel_launch(void* const* d_in, const int* in_sizes, int n_in,
                              void* d_out, int out_size) {
    const float* x     = (const float*)d_in[0];
    const float* ln_w  = (const float*)d_in[1];
    const float* ln_b  = (const float*)d_in[2];
    const float* wq    = (const float*)d_in[3];
    const float* wk    = (const float*)d_in[4];
    const float* wv_v  = (const float*)d_in[5];
    const float* wv_g  = (const float*)d_in[6];
    const float* w_out = (const float*)d_in[7];
    float* out = (float*)d_out;

    __half *xnh, *ath, *qh, *kh, *vh;
    __half *wqh, *wkh, *wvh, *woh, *wol;
    cudaGetSymbolAddress((void**)&xnh, g_xnh);
    cudaGetSymbolAddress((void**)&ath, g_ath);
    cudaGetSymbolAddress((void**)&qh, g_qh);
    cudaGetSymbolAddress((void**)&kh, g_kh);
    cudaGetSymbolAddress((void**)&vh, g_vh);
    cudaGetSymbolAddress((void**)&wqh, g_wqh);
    cudaGetSymbolAddress((void**)&wkh, g_wkh);
    cudaGetSymbolAddress((void**)&wvh, g_wvh);
    cudaGetSymbolAddress((void**)&woh, g_woh);
    cudaGetSymbolAddress((void**)&wol, g_wol);

    cudaFuncSetAttribute(gemm1, cudaFuncAttributeMaxDynamicSharedMemorySize, G1_SMEM);
    cudaFuncSetAttribute(gemmO, cudaFuncAttributeMaxDynamicSharedMemorySize, GO_SMEM);
    cudaFuncSetAttribute(attn_mma, cudaFuncAttributeMaxDynamicSharedMemorySize, A_SMEM);

    const float QSCALE = 0.125f * 1.44269504088896f;  // (1/8) * log2(e)

    prep_kernel<<<ROWS + DIM * DIM / 256 + DIM, 256>>>(x, ln_w, ln_b, wq, wk, w_out, wv_v, wv_g);

    gemm1<<<dim3(DIM / 128, ROWS / 128), 256, G1_SMEM>>>(xnh,
                                                         wqh, qh, QSCALE,
                                                         wkh, kh, 1.0f,
                                                         wvh, vh, 1.0f);

    attn_mma<<<dim3(32, 8), 256, A_SMEM>>>(qh, kh, vh, ath);

    gemmO<<<dim3(DIM / 128, ROWS / 128), 256, GO_SMEM>>>(ath, woh, wol, out);
}

// round 16
// speedup vs baseline: 1.0722x; 1.0722x over previous
#include <cuda_runtime.h>
#include <cuda_fp16.h>
#include <cstdint>

#define DIM 512
#define HEADS 8
#define DHEAD 64
#define BATCH 4
#define NSEQ 2048
#define ROWS (BATCH * NSEQ)   // 8192

// ================= scratch (no allocations allowed) =================
__device__ __half g_xnh[ROWS * DIM];
__device__ __half g_qh[ROWS * DIM];
__device__ __half g_kh[ROWS * DIM];
__device__ __half g_vh[ROWS * DIM];
__device__ __half g_ath[ROWS * DIM];
__device__ __half g_wqh[DIM * DIM];
__device__ __half g_wkh[DIM * DIM];
__device__ __half g_wvh[DIM * DIM];
__device__ __half g_woh[DIM * DIM], g_wol[DIM * DIM];

// ================= helpers =================
__device__ __forceinline__ uint32_t smem_u32(const void* p) {
    uint32_t a;
    asm("{ .reg .u64 t; cvta.to.shared.u64 t, %1; cvt.u32.u64 %0, t; }" : "=r"(a) : "l"(p));
    return a;
}
__device__ __forceinline__ void ldsm4(uint32_t* r, uint32_t a) {
    asm volatile("ldmatrix.sync.aligned.m8n8.x4.shared.b16 {%0,%1,%2,%3}, [%4];"
                 : "=r"(r[0]), "=r"(r[1]), "=r"(r[2]), "=r"(r[3]) : "r"(a));
}
__device__ __forceinline__ void ldsm4t(uint32_t* r, uint32_t a) {
    asm volatile("ldmatrix.sync.aligned.m8n8.x4.trans.shared.b16 {%0,%1,%2,%3}, [%4];"
                 : "=r"(r[0]), "=r"(r[1]), "=r"(r[2]), "=r"(r[3]) : "r"(a));
}
__device__ __forceinline__ void mmaf32(float* c, const uint32_t* a, const uint32_t* b) {
    asm volatile("mma.sync.aligned.m16n8k16.row.col.f32.f16.f16.f32 "
                 "{%0,%1,%2,%3}, {%4,%5,%6,%7}, {%8,%9}, {%0,%1,%2,%3};"
                 : "+f"(c[0]), "+f"(c[1]), "+f"(c[2]), "+f"(c[3])
                 : "r"(a[0]), "r"(a[1]), "r"(a[2]), "r"(a[3]), "r"(b[0]), "r"(b[1]));
}
__device__ __forceinline__ void cpa16(uint32_t d, const void* s) {
    asm volatile("cp.async.cg.shared.global [%0], [%1], 16;" :: "r"(d), "l"(s));
}
#define CP_COMMIT() asm volatile("cp.async.commit_group;")
#define CP_WAIT(n)  asm volatile("cp.async.wait_group %0;" :: "n"(n))

__device__ __forceinline__ uint32_t h2pack(float a, float b) {
    __half2 t = __floats2half2_rn(a, b);
    return *reinterpret_cast<uint32_t*>(&t);
}
__device__ __forceinline__ float hres(float a) {
    __half h = __float2half_rn(a);
    return a - __half2float(h);
}

// ================= fused prep: ln (0..8191) + conv3 (8192..9215) + wnorm (9216..9727) =================
__global__ __launch_bounds__(256) void prep_kernel(const float* __restrict__ x,
                                                   const float* __restrict__ w,
                                                   const float* __restrict__ b,
                                                   const float* __restrict__ wq,
                                                   const float* __restrict__ wk,
                                                   const float* __restrict__ wo,
                                                   const float* __restrict__ wv_v,
                                                   const float* __restrict__ wv_g) {
    int t = threadIdx.x;
    if (blockIdx.x < ROWS) {
        __shared__ float sb1[8], sb2[8];
        int row = blockIdx.x;
        const float* xr = x + (size_t)row * DIM;
        float v0 = xr[t], v1 = xr[t + 256];
        float s = v0 + v1, ss = v0 * v0 + v1 * v1;
        #pragma unroll
        for (int o = 16; o > 0; o >>= 1) {
            s  += __shfl_xor_sync(~0u, s, o);
            ss += __shfl_xor_sync(~0u, ss, o);
        }
        int lane = t & 31, wd = t >> 5;
        if (lane == 0) { sb1[wd] = s; sb2[wd] = ss; }
        __syncthreads();
        if (wd == 0) {
            float r1 = (lane < 8) ? sb1[lane] : 0.f, r2 = (lane < 8) ? sb2[lane] : 0.f;
            #pragma unroll
            for (int o = 4; o > 0; o >>= 1) {
                r1 += __shfl_xor_sync(~0u, r1, o);
                r2 += __shfl_xor_sync(~0u, r2, o);
            }
            if (lane == 0) { sb1[0] = r1; sb2[0] = r2; }
        }
        __syncthreads();
        float mu  = sb1[0] * (1.f / DIM);
        float var = sb2[0] * (1.f / DIM) - mu * mu;
        float inv = rsqrtf(var + 1e-5f);
        size_t base = (size_t)row * DIM;
        g_xnh[base + t]       = __float2half_rn((v0 - mu) * inv * w[t] + b[t]);
        g_xnh[base + t + 256] = __float2half_rn((v1 - mu) * inv * w[t + 256] + b[t + 256]);
    } else if (blockIdx.x < ROWS + DIM * DIM / 256) {
        int i = (blockIdx.x - ROWS) * 256 + t;
        g_wqh[i] = __float2half_rn(wq[i]);
        g_wkh[i] = __float2half_rn(wk[i]);
        float f2 = wo[i];
        g_woh[i] = __float2half_rn(f2);
        g_wol[i] = __float2half_rn(hres(f2));
    } else {
        __shared__ float sbuf[8];
        int row = blockIdx.x - (ROWS + DIM * DIM / 256);
        const float* vr = wv_v + (size_t)row * DIM;
        float v0 = vr[t], v1 = vr[t + 256];
        float ss = v0 * v0 + v1 * v1;
        #pragma unroll
        for (int o = 16; o > 0; o >>= 1) ss += __shfl_xor_sync(~0u, ss, o);
        int lane = t & 31, wd = t >> 5;
        if (lane == 0) sbuf[wd] = ss;
        __syncthreads();
        if (wd == 0) {
            float r = (lane < 8) ? sbuf[lane] : 0.f;
            #pragma unroll
            for (int o = 4; o > 0; o >>= 1) r += __shfl_xor_sync(~0u, r, o);
            if (lane == 0) sbuf[0] = r;
        }
        __syncthreads();
        float sc = wv_g[row] * rsqrtf(sbuf[0]);
        size_t base = (size_t)row * DIM;
        g_wvh[base + t]       = __float2half_rn(v0 * sc);
        g_wvh[base + t + 256] = __float2half_rn(v1 * sc);
    }
}

#define GP 144
#define TT (128 * GP)          // 18432 per tile

// ================= 1-term fp16 GEMM (QKV, fused over z) — R14 form =================
#define ST1 (2 * TT)           // 36864 per stage
#define G1_SMEM (2 * ST1)      // 73728

__global__ __launch_bounds__(256, 2)
void gemm1(const __half* __restrict__ Ah,
           const __half* __restrict__ B0, __half* __restrict__ C0, float s0,
           const __half* __restrict__ B1, __half* __restrict__ C1, float s1,
           const __half* __restrict__ B2, __half* __restrict__ C2, float s2) {
    const __half* Bh = blockIdx.z == 0 ? B0 : (blockIdx.z == 1 ? B1 : B2);
    __half* Ch = blockIdx.z == 0 ? C0 : (blockIdx.z == 1 ? C1 : C2);
    float scale = blockIdx.z == 0 ? s0 : (blockIdx.z == 1 ? s1 : s2);

    extern __shared__ char sm[];
    uint32_t sb = smem_u32(sm);
    int tid = threadIdx.x, lane = tid & 31, wd = tid >> 5;
    int wm = wd & 3, wn = wd >> 2;
    int tm = blockIdx.y * 128, tn = blockIdx.x * 128;

    float c[2][8][4];
    #pragma unroll
    for (int i = 0; i < 2; i++)
        #pragma unroll
        for (int j = 0; j < 8; j++)
            #pragma unroll
            for (int e = 0; e < 4; e++) c[i][j][e] = 0.f;

    auto stage = [&](int kc, uint32_t buf) {
        int k0 = kc * 64;
        #pragma unroll
        for (int u = 0; u < 4; u++) {
            int e = tid + u * 256;
            int r = e >> 3, c8 = (e & 7) * 8;
            uint32_t d = buf + (uint32_t)r * GP + c8 * 2;
            cpa16(d, &Ah[(size_t)(tm + r) * DIM + k0 + c8]);
            cpa16(d + TT, &Bh[(size_t)(tn + r) * DIM + k0 + c8]);
        }
    };

    stage(0, sb);
    CP_COMMIT();

    for (int kc = 0; kc < 8; kc++) {
        CP_WAIT(0);
        __syncthreads();
        if (kc < 7) {
            stage(kc + 1, sb + ((kc + 1) & 1) * ST1);
            CP_COMMIT();
        }
        uint32_t buf = sb + (kc & 1) * ST1;
        #pragma unroll
        for (int ks = 0; ks < 4; ks++) {
            uint32_t ah[2][4];
            uint32_t acol = ks * 32 + ((lane >> 4) << 4);
            #pragma unroll
            for (int mt = 0; mt < 2; mt++) {
                uint32_t arow = wm * 32 + mt * 16 + (lane & 15);
                ldsm4(ah[mt], buf + arow * GP + acol);
            }
            uint32_t bro = ((lane >> 4) << 3) + (lane & 7);
            uint32_t bcol = ks * 32 + (((lane >> 3) & 1) << 4);
            #pragma unroll
            for (int p = 0; p < 4; p++) {
                uint32_t nrow = wn * 64 + p * 16 + bro;
                uint32_t bh[4];
                ldsm4(bh, buf + TT + nrow * GP + bcol);
                #pragma unroll
                for (int mt = 0; mt < 2; mt++) {
                    mmaf32(c[mt][2 * p],     ah[mt], &bh[0]);
                    mmaf32(c[mt][2 * p + 1], ah[mt], &bh[2]);
                }
            }
        }
        __syncthreads();
    }

    int g = lane >> 2, t4 = lane & 3;
    #pragma unroll
    for (int mt = 0; mt < 2; mt++) {
        #pragma unroll
        for (int nt = 0; nt < 8; nt++) {
            int row = tm + wm * 32 + mt * 16 + g;
            int col = tn + wn * 64 + nt * 8 + t4 * 2;
            *(uint32_t*)&Ch[(size_t)row * DIM + col] =
                h2pack(c[mt][nt][0] * scale, c[mt][nt][1] * scale);
            *(uint32_t*)&Ch[(size_t)(row + 8) * DIM + col] =
                h2pack(c[mt][nt][2] * scale, c[mt][nt][3] * scale);
        }
    }
}

// ================= 2-term output GEMM: C_f = A_h * (B_h + B_l)^T, occ 2 =================
#define STO (3 * TT)           // 55296 per stage
#define GO_SMEM (2 * STO)      // 110592

__global__ __launch_bounds__(256, 2)
void gemmO(const __half* __restrict__ Ah,
           const __half* __restrict__ Bh, const __half* __restrict__ Bl,
           float* __restrict__ Cf) {
    extern __shared__ char sm[];
    uint32_t sb = smem_u32(sm);
    int tid = threadIdx.x, lane = tid & 31, wd = tid >> 5;
    int wm = wd & 3, wn = wd >> 2;
    int tm = blockIdx.y * 128, tn = blockIdx.x * 128;

    float c[2][8][4];
    #pragma unroll
    for (int i = 0; i < 2; i++)
        #pragma unroll
        for (int j = 0; j < 8; j++)
            #pragma unroll
            for (int e = 0; e < 4; e++) c[i][j][e] = 0.f;

    auto stage = [&](int kc, uint32_t buf) {
        int k0 = kc * 64;
        #pragma unroll
        for (int u = 0; u < 4; u++) {
            int e = tid + u * 256;
            int r = e >> 3, c8 = (e & 7) * 8;
            uint32_t d = buf + (uint32_t)r * GP + c8 * 2;
            cpa16(d, &Ah[(size_t)(tm + r) * DIM + k0 + c8]);
            cpa16(d + TT, &Bh[(size_t)(tn + r) * DIM + k0 + c8]);
            cpa16(d + 2 * TT, &Bl[(size_t)(tn + r) * DIM + k0 + c8]);
        }
    };

    stage(0, sb);
    CP_COMMIT();

    for (int kc = 0; kc < 8; kc++) {
        CP_WAIT(0);
        __syncthreads();
        if (kc < 7) {
            stage(kc + 1, sb + ((kc + 1) & 1) * STO);
            CP_COMMIT();
        }
        uint32_t buf = sb + (kc & 1) * STO;
        #pragma unroll
        for (int ks = 0; ks < 4; ks++) {
            uint32_t ah[2][4];
            uint32_t acol = ks * 32 + ((lane >> 4) << 4);
            #pragma unroll
            for (int mt = 0; mt < 2; mt++) {
                uint32_t arow = wm * 32 + mt * 16 + (lane & 15);
                ldsm4(ah[mt], buf + arow * GP + acol);
            }
            uint32_t bro = ((lane >> 4) << 3) + (lane & 7);
            uint32_t bcol = ks * 32 + (((lane >> 3) & 1) << 4);
            #pragma unroll
            for (int p = 0; p < 4; p++) {
                uint32_t nrow = wn * 64 + p * 16 + bro;
                uint32_t bh[4], bl[4];
                ldsm4(bh, buf + TT + nrow * GP + bcol);
                ldsm4(bl, buf + 2 * TT + nrow * GP + bcol);
                #pragma unroll
                for (int mt = 0; mt < 2; mt++) {
                    mmaf32(c[mt][2 * p],     ah[mt], &bh[0]);
                    mmaf32(c[mt][2 * p],     ah[mt], &bl[0]);
                    mmaf32(c[mt][2 * p + 1], ah[mt], &bh[2]);
                    mmaf32(c[mt][2 * p + 1], ah[mt], &bl[2]);
                }
            }
        }
        __syncthreads();
    }

    int g = lane >> 2, t4 = lane & 3;
    #pragma unroll
    for (int mt = 0; mt < 2; mt++) {
        #pragma unroll
        for (int nt = 0; nt < 8; nt++) {
            int row = tm + wm * 32 + mt * 16 + g;
            int col = tn + wn * 64 + nt * 8 + t4 * 2;
            *(float2*)&Cf[(size_t)row * DIM + col] =
                make_float2(c[mt][nt][0], c[mt][nt][1]);
            *(float2*)&Cf[(size_t)(row + 8) * DIM + col] =
                make_float2(c[mt][nt][2], c[mt][nt][3]);
        }
    }
}

// ================= flash attention: 1-term fp16, exp2, occ 2 — R14 form =================
#define AST (64 * GP)           // 9216 per tile
#define A_SMEM (2 * 2 * AST)    // 36864

__global__ __launch_bounds__(256, 2)
void attn_mma(const __half* __restrict__ Qh,
              const __half* __restrict__ Kh,
              const __half* __restrict__ Vh,
              __half* __restrict__ Oh) {
    extern __shared__ char sm[];
    uint32_t sb = smem_u32(sm);
    int tid = threadIdx.x, lane = tid & 31, wd = tid >> 5;
    int b = blockIdx.x >> 3, h = blockIdx.x & 7;
    int iBase = blockIdx.y * 128;
    size_t base = (size_t)b * NSEQ * DIM + (size_t)h * DHEAD;

    #pragma unroll
    for (int u = 0; u < 4; u++) {
        int e = tid + u * 256;
        int r = e >> 3, c8 = (e & 7) * 8;
        uint32_t d = sb + (uint32_t)r * GP + c8 * 2;
        cpa16(d, &Qh[base + (size_t)(iBase + r) * DIM + c8]);
    }
    CP_COMMIT(); CP_WAIT(0);
    __syncthreads();

    uint32_t qh[4][4];
    {
        uint32_t arow = wd * 16 + (lane & 15);
        #pragma unroll
        for (int ks = 0; ks < 4; ks++) {
            uint32_t acol = ks * 32 + ((lane >> 4) << 4);
            ldsm4(qh[ks], sb + arow * GP + acol);
        }
    }
    __syncthreads();

    float o[8][4];
    #pragma unroll
    for (int i = 0; i < 8; i++)
        #pragma unroll
        for (int e = 0; e < 4; e++) o[i][e] = 0.f;
    float l0 = 0.f, l1 = 0.f;

    auto stage_kv = [&](int blk, uint32_t buf) {
        int j0 = blk * 64;
        #pragma unroll
        for (int u = 0; u < 2; u++) {
            int e = tid + u * 256;
            int r = e >> 3, c8 = (e & 7) * 8;
            uint32_t d = buf + (uint32_t)r * GP + c8 * 2;
            size_t ga = base + (size_t)(j0 + r) * DIM + c8;
            cpa16(d, &Kh[ga]);
            cpa16(d + AST, &Vh[ga]);
        }
    };

    stage_kv(0, sb);
    CP_COMMIT();

    for (int bi = 0; bi < 32; bi++) {
        CP_WAIT(0);
        __syncthreads();
        uint32_t buf = sb + (bi & 1) * 2 * AST;
        if (bi < 31) {
            stage_kv(bi + 1, sb + ((bi + 1) & 1) * 2 * AST);
            CP_COMMIT();
        }

        float s[8][4];
        #pragma unroll
        for (int nt = 0; nt < 8; nt++)
            #pragma unroll
            for (int e = 0; e < 4; e++) s[nt][e] = 0.f;

        uint32_t bro = ((lane >> 4) << 3) + (lane & 7);
        #pragma unroll
        for (int ks = 0; ks < 4; ks++) {
            uint32_t bcol = ks * 32 + (((lane >> 3) & 1) << 4);
            #pragma unroll
            for (int p = 0; p < 4; p++) {
                uint32_t nrow = p * 16 + bro;
                uint32_t bh[4];
                ldsm4(bh, buf + nrow * GP + bcol);
                mmaf32(s[2 * p],     qh[ks], &bh[0]);
                mmaf32(s[2 * p + 1], qh[ks], &bh[2]);
            }
        }

        #pragma unroll
        for (int nt = 0; nt < 8; nt++) {
            s[nt][0] = exp2f(s[nt][0]);
            s[nt][1] = exp2f(s[nt][1]);
            s[nt][2] = exp2f(s[nt][2]);
            s[nt][3] = exp2f(s[nt][3]);
            l0 += s[nt][0] + s[nt][1];
            l1 += s[nt][2] + s[nt][3];
        }

        uint32_t vro = (((lane >> 3) & 1) << 3) + (lane & 7);
        uint32_t vco = (lane >> 4) << 4;
        #pragma unroll
        for (int st = 0; st < 4; st++) {
            uint32_t a_h[4];
            a_h[0] = h2pack(s[2 * st][0], s[2 * st][1]);
            a_h[1] = h2pack(s[2 * st][2], s[2 * st][3]);
            a_h[2] = h2pack(s[2 * st + 1][0], s[2 * st + 1][1]);
            a_h[3] = h2pack(s[2 * st + 1][2], s[2 * st + 1][3]);
            uint32_t jrow = st * 16 + vro;
            #pragma unroll
            for (int dp = 0; dp < 4; dp++) {
                uint32_t db = dp * 32 + vco;
                uint32_t vh[4];
                ldsm4t(vh, buf + AST + jrow * GP + db);
                mmaf32(o[2 * dp],     a_h, &vh[0]);
                mmaf32(o[2 * dp + 1], a_h, &vh[2]);
            }
        }
        __syncthreads();
    }

    l0 += __shfl_xor_sync(~0u, l0, 1); l0 += __shfl_xor_sync(~0u, l0, 2);
    l1 += __shfl_xor_sync(~0u, l1, 1); l1 += __shfl_xor_sync(~0u, l1, 2);
    float i0v = 1.f / l0, i1v = 1.f / l1;

    int g = lane >> 2, t4 = lane & 3;
    size_t ga0 = base + (size_t)(iBase + wd * 16 + g) * DIM + t4 * 2;
    size_t ga1 = ga0 + 8 * DIM;
    #pragma unroll
    for (int dt = 0; dt < 8; dt++) {
        *(uint32_t*)&Oh[ga0 + dt * 8] = h2pack(o[dt][0] * i0v, o[dt][1] * i0v);
        *(uint32_t*)&Oh[ga1 + dt * 8] = h2pack(o[dt][2] * i1v, o[dt][3] * i1v);
    }
}

// ================= launch =================
extern "C" void kernel_launch(void* const* d_in, const int* in_sizes, int n_in,
                              void* d_out, int out_size) {
    const float* x     = (const float*)d_in[0];
    const float* ln_w  = (const float*)d_in[1];
    const float* ln_b  = (const float*)d_in[2];
    const float* wq    = (const float*)d_in[3];
    const float* wk    = (const float*)d_in[4];
    const float* wv_v  = (const float*)d_in[5];
    const float* wv_g  = (const float*)d_in[6];
    const float* w_out = (const float*)d_in[7];
    float* out = (float*)d_out;

    __half *xnh, *ath, *qh, *kh, *vh;
    __half *wqh, *wkh, *wvh, *woh, *wol;
    cudaGetSymbolAddress((void**)&xnh, g_xnh);
    cudaGetSymbolAddress((void**)&ath, g_ath);
    cudaGetSymbolAddress((void**)&qh, g_qh);
    cudaGetSymbolAddress((void**)&kh, g_kh);
    cudaGetSymbolAddress((void**)&vh, g_vh);
    cudaGetSymbolAddress((void**)&wqh, g_wqh);
    cudaGetSymbolAddress((void**)&wkh, g_wkh);
    cudaGetSymbolAddress((void**)&wvh, g_wvh);
    cudaGetSymbolAddress((void**)&woh, g_woh);
    cudaGetSymbolAddress((void**)&wol, g_wol);

    cudaFuncSetAttribute(gemm1, cudaFuncAttributeMaxDynamicSharedMemorySize, G1_SMEM);
    cudaFuncSetAttribute(gemmO, cudaFuncAttributeMaxDynamicSharedMemorySize, GO_SMEM);
    cudaFuncSetAttribute(attn_mma, cudaFuncAttributeMaxDynamicSharedMemorySize, A_SMEM);

    const float QSCALE = 0.125f * 1.44269504088896f;  // (1/8) * log2(e)

    prep_kernel<<<ROWS + DIM * DIM / 256 + DIM, 256>>>(x, ln_w, ln_b, wq, wk, w_out, wv_v, wv_g);

    dim3 gqkv(DIM / 128, ROWS / 128, 3);
    gemm1<<<gqkv, 256, G1_SMEM>>>(xnh,
                                  wqh, qh, QSCALE,
                                  wkh, kh, 1.0f,
                                  wvh, vh, 1.0f);

    attn_mma<<<dim3(32, 16), 256, A_SMEM>>>(qh, kh, vh, ath);

    gemmO<<<dim3(DIM / 128, ROWS / 128), 256, GO_SMEM>>>(ath, woh, wol, out);
}

// round 17
// speedup vs baseline: 1.1429x; 1.0659x over previous
#include <cuda_runtime.h>
#include <cuda_fp16.h>
#include <cstdint>

#define DIM 512
#define HEADS 8
#define DHEAD 64
#define BATCH 4
#define NSEQ 2048
#define ROWS (BATCH * NSEQ)   // 8192

// ================= scratch (no allocations allowed) =================
__device__ __half g_xnh[ROWS * DIM];
__device__ __half g_qh[ROWS * DIM];
__device__ __half g_kh[ROWS * DIM];
__device__ __half g_vh[ROWS * DIM];
__device__ __half g_ath[ROWS * DIM];
__device__ __half g_wqh[DIM * DIM];
__device__ __half g_wkh[DIM * DIM];
__device__ __half g_wvh[DIM * DIM];
__device__ __half g_woh[DIM * DIM];

// ================= helpers =================
__device__ __forceinline__ uint32_t smem_u32(const void* p) {
    uint32_t a;
    asm("{ .reg .u64 t; cvta.to.shared.u64 t, %1; cvt.u32.u64 %0, t; }" : "=r"(a) : "l"(p));
    return a;
}
__device__ __forceinline__ void ldsm4(uint32_t* r, uint32_t a) {
    asm volatile("ldmatrix.sync.aligned.m8n8.x4.shared.b16 {%0,%1,%2,%3}, [%4];"
                 : "=r"(r[0]), "=r"(r[1]), "=r"(r[2]), "=r"(r[3]) : "r"(a));
}
__device__ __forceinline__ void ldsm4t(uint32_t* r, uint32_t a) {
    asm volatile("ldmatrix.sync.aligned.m8n8.x4.trans.shared.b16 {%0,%1,%2,%3}, [%4];"
                 : "=r"(r[0]), "=r"(r[1]), "=r"(r[2]), "=r"(r[3]) : "r"(a));
}
__device__ __forceinline__ void mmaf32(float* c, const uint32_t* a, const uint32_t* b) {
    asm volatile("mma.sync.aligned.m16n8k16.row.col.f32.f16.f16.f32 "
                 "{%0,%1,%2,%3}, {%4,%5,%6,%7}, {%8,%9}, {%0,%1,%2,%3};"
                 : "+f"(c[0]), "+f"(c[1]), "+f"(c[2]), "+f"(c[3])
                 : "r"(a[0]), "r"(a[1]), "r"(a[2]), "r"(a[3]), "r"(b[0]), "r"(b[1]));
}
__device__ __forceinline__ void cpa16(uint32_t d, const void* s) {
    asm volatile("cp.async.cg.shared.global [%0], [%1], 16;" :: "r"(d), "l"(s));
}
#define CP_COMMIT() asm volatile("cp.async.commit_group;")
#define CP_WAIT(n)  asm volatile("cp.async.wait_group %0;" :: "n"(n))

__device__ __forceinline__ uint32_t h2pack(float a, float b) {
    __half2 t = __floats2half2_rn(a, b);
    return *reinterpret_cast<uint32_t*>(&t);
}

// ================= fused prep: ln (0..8191) + conv3 (8192..9215) + wnorm (9216..9727) =================
__global__ __launch_bounds__(256) void prep_kernel(const float* __restrict__ x,
                                                   const float* __restrict__ w,
                                                   const float* __restrict__ b,
                                                   const float* __restrict__ wq,
                                                   const float* __restrict__ wk,
                                                   const float* __restrict__ wo,
                                                   const float* __restrict__ wv_v,
                                                   const float* __restrict__ wv_g) {
    int t = threadIdx.x;
    if (blockIdx.x < ROWS) {
        __shared__ float sb1[8], sb2[8];
        int row = blockIdx.x;
        const float* xr = x + (size_t)row * DIM;
        float v0 = xr[t], v1 = xr[t + 256];
        float s = v0 + v1, ss = v0 * v0 + v1 * v1;
        #pragma unroll
        for (int o = 16; o > 0; o >>= 1) {
            s  += __shfl_xor_sync(~0u, s, o);
            ss += __shfl_xor_sync(~0u, ss, o);
        }
        int lane = t & 31, wd = t >> 5;
        if (lane == 0) { sb1[wd] = s; sb2[wd] = ss; }
        __syncthreads();
        if (wd == 0) {
            float r1 = (lane < 8) ? sb1[lane] : 0.f, r2 = (lane < 8) ? sb2[lane] : 0.f;
            #pragma unroll
            for (int o = 4; o > 0; o >>= 1) {
                r1 += __shfl_xor_sync(~0u, r1, o);
                r2 += __shfl_xor_sync(~0u, r2, o);
            }
            if (lane == 0) { sb1[0] = r1; sb2[0] = r2; }
        }
        __syncthreads();
        float mu  = sb1[0] * (1.f / DIM);
        float var = sb2[0] * (1.f / DIM) - mu * mu;
        float inv = rsqrtf(var + 1e-5f);
        size_t base = (size_t)row * DIM;
        g_xnh[base + t]       = __float2half_rn((v0 - mu) * inv * w[t] + b[t]);
        g_xnh[base + t + 256] = __float2half_rn((v1 - mu) * inv * w[t + 256] + b[t + 256]);
    } else if (blockIdx.x < ROWS + DIM * DIM / 256) {
        int i = (blockIdx.x - ROWS) * 256 + t;
        g_wqh[i] = __float2half_rn(wq[i]);
        g_wkh[i] = __float2half_rn(wk[i]);
        g_woh[i] = __float2half_rn(wo[i]);
    } else {
        __shared__ float sbuf[8];
        int row = blockIdx.x - (ROWS + DIM * DIM / 256);
        const float* vr = wv_v + (size_t)row * DIM;
        float v0 = vr[t], v1 = vr[t + 256];
        float ss = v0 * v0 + v1 * v1;
        #pragma unroll
        for (int o = 16; o > 0; o >>= 1) ss += __shfl_xor_sync(~0u, ss, o);
        int lane = t & 31, wd = t >> 5;
        if (lane == 0) sbuf[wd] = ss;
        __syncthreads();
        if (wd == 0) {
            float r = (lane < 8) ? sbuf[lane] : 0.f;
            #pragma unroll
            for (int o = 4; o > 0; o >>= 1) r += __shfl_xor_sync(~0u, r, o);
            if (lane == 0) sbuf[0] = r;
        }
        __syncthreads();
        float sc = wv_g[row] * rsqrtf(sbuf[0]);
        size_t base = (size_t)row * DIM;
        g_wvh[base + t]       = __float2half_rn(v0 * sc);
        g_wvh[base + t + 256] = __float2half_rn(v1 * sc);
    }
}

#define GP 144
#define TT (128 * GP)          // 18432 per tile

// ================= 1-term fp16 GEMM =================
// MODE 0: fp16 out (QKV, z-fused). MODE 1: fp32 out (output projection).
#define ST1 (2 * TT)           // 36864 per stage
#define G1_SMEM (2 * ST1)      // 73728

template <int MODE>
__global__ __launch_bounds__(256, 2)
void gemm1(const __half* __restrict__ Ah,
           const __half* __restrict__ B0, __half* __restrict__ C0, float s0,
           const __half* __restrict__ B1, __half* __restrict__ C1, float s1,
           const __half* __restrict__ B2, __half* __restrict__ C2, float s2,
           float* __restrict__ Cf) {
    const __half* Bh = blockIdx.z == 0 ? B0 : (blockIdx.z == 1 ? B1 : B2);
    __half* Ch = blockIdx.z == 0 ? C0 : (blockIdx.z == 1 ? C1 : C2);
    float scale = blockIdx.z == 0 ? s0 : (blockIdx.z == 1 ? s1 : s2);

    extern __shared__ char sm[];
    uint32_t sb = smem_u32(sm);
    int tid = threadIdx.x, lane = tid & 31, wd = tid >> 5;
    int wm = wd & 3, wn = wd >> 2;
    int tm = blockIdx.y * 128, tn = blockIdx.x * 128;

    float c[2][8][4];
    #pragma unroll
    for (int i = 0; i < 2; i++)
        #pragma unroll
        for (int j = 0; j < 8; j++)
            #pragma unroll
            for (int e = 0; e < 4; e++) c[i][j][e] = 0.f;

    auto stage = [&](int kc, uint32_t buf) {
        int k0 = kc * 64;
        #pragma unroll
        for (int u = 0; u < 4; u++) {
            int e = tid + u * 256;
            int r = e >> 3, c8 = (e & 7) * 8;
            uint32_t d = buf + (uint32_t)r * GP + c8 * 2;
            cpa16(d, &Ah[(size_t)(tm + r) * DIM + k0 + c8]);
            cpa16(d + TT, &Bh[(size_t)(tn + r) * DIM + k0 + c8]);
        }
    };

    stage(0, sb);
    CP_COMMIT();

    for (int kc = 0; kc < 8; kc++) {
        CP_WAIT(0);
        __syncthreads();
        if (kc < 7) {
            stage(kc + 1, sb + ((kc + 1) & 1) * ST1);
            CP_COMMIT();
        }
        uint32_t buf = sb + (kc & 1) * ST1;
        #pragma unroll
        for (int ks = 0; ks < 4; ks++) {
            uint32_t ah[2][4];
            uint32_t acol = ks * 32 + ((lane >> 4) << 4);
            #pragma unroll
            for (int mt = 0; mt < 2; mt++) {
                uint32_t arow = wm * 32 + mt * 16 + (lane & 15);
                ldsm4(ah[mt], buf + arow * GP + acol);
            }
            uint32_t bro = ((lane >> 4) << 3) + (lane & 7);
            uint32_t bcol = ks * 32 + (((lane >> 3) & 1) << 4);
            #pragma unroll
            for (int p = 0; p < 4; p++) {
                uint32_t nrow = wn * 64 + p * 16 + bro;
                uint32_t bh[4];
                ldsm4(bh, buf + TT + nrow * GP + bcol);
                #pragma unroll
                for (int mt = 0; mt < 2; mt++) {
                    mmaf32(c[mt][2 * p],     ah[mt], &bh[0]);
                    mmaf32(c[mt][2 * p + 1], ah[mt], &bh[2]);
                }
            }
        }
        __syncthreads();
    }

    int g = lane >> 2, t4 = lane & 3;
    #pragma unroll
    for (int mt = 0; mt < 2; mt++) {
        #pragma unroll
        for (int nt = 0; nt < 8; nt++) {
            int row = tm + wm * 32 + mt * 16 + g;
            int col = tn + wn * 64 + nt * 8 + t4 * 2;
            if (MODE == 0) {
                *(uint32_t*)&Ch[(size_t)row * DIM + col] =
                    h2pack(c[mt][nt][0] * scale, c[mt][nt][1] * scale);
                *(uint32_t*)&Ch[(size_t)(row + 8) * DIM + col] =
                    h2pack(c[mt][nt][2] * scale, c[mt][nt][3] * scale);
            } else {
                *(float2*)&Cf[(size_t)row * DIM + col] =
                    make_float2(c[mt][nt][0], c[mt][nt][1]);
                *(float2*)&Cf[(size_t)(row + 8) * DIM + col] =
                    make_float2(c[mt][nt][2], c[mt][nt][3]);
            }
        }
    }
}

// ================= flash attention: 1-term fp16, exp2, occ 2 =================
#define AST (64 * GP)           // 9216 per tile
#define A_SMEM (2 * 2 * AST)    // 36864

__global__ __launch_bounds__(256, 2)
void attn_mma(const __half* __restrict__ Qh,
              const __half* __restrict__ Kh,
              const __half* __restrict__ Vh,
              __half* __restrict__ Oh) {
    extern __shared__ char sm[];
    uint32_t sb = smem_u32(sm);
    int tid = threadIdx.x, lane = tid & 31, wd = tid >> 5;
    int b = blockIdx.x >> 3, h = blockIdx.x & 7;
    int iBase = blockIdx.y * 128;
    size_t base = (size_t)b * NSEQ * DIM + (size_t)h * DHEAD;

    #pragma unroll
    for (int u = 0; u < 4; u++) {
        int e = tid + u * 256;
        int r = e >> 3, c8 = (e & 7) * 8;
        uint32_t d = sb + (uint32_t)r * GP + c8 * 2;
        cpa16(d, &Qh[base + (size_t)(iBase + r) * DIM + c8]);
    }
    CP_COMMIT(); CP_WAIT(0);
    __syncthreads();

    uint32_t qh[4][4];
    {
        uint32_t arow = wd * 16 + (lane & 15);
        #pragma unroll
        for (int ks = 0; ks < 4; ks++) {
            uint32_t acol = ks * 32 + ((lane >> 4) << 4);
            ldsm4(qh[ks], sb + arow * GP + acol);
        }
    }
    __syncthreads();

    float o[8][4];
    #pragma unroll
    for (int i = 0; i < 8; i++)
        #pragma unroll
        for (int e = 0; e < 4; e++) o[i][e] = 0.f;
    float l0 = 0.f, l1 = 0.f;

    auto stage_kv = [&](int blk, uint32_t buf) {
        int j0 = blk * 64;
        #pragma unroll
        for (int u = 0; u < 2; u++) {
            int e = tid + u * 256;
            int r = e >> 3, c8 = (e & 7) * 8;
            uint32_t d = buf + (uint32_t)r * GP + c8 * 2;
            size_t ga = base + (size_t)(j0 + r) * DIM + c8;
            cpa16(d, &Kh[ga]);
            cpa16(d + AST, &Vh[ga]);
        }
    };

    stage_kv(0, sb);
    CP_COMMIT();

    for (int bi = 0; bi < 32; bi++) {
        CP_WAIT(0);
        __syncthreads();
        uint32_t buf = sb + (bi & 1) * 2 * AST;
        if (bi < 31) {
            stage_kv(bi + 1, sb + ((bi + 1) & 1) * 2 * AST);
            CP_COMMIT();
        }

        float s[8][4];
        #pragma unroll
        for (int nt = 0; nt < 8; nt++)
            #pragma unroll
            for (int e = 0; e < 4; e++) s[nt][e] = 0.f;

        uint32_t bro = ((lane >> 4) << 3) + (lane & 7);
        #pragma unroll
        for (int ks = 0; ks < 4; ks++) {
            uint32_t bcol = ks * 32 + (((lane >> 3) & 1) << 4);
            #pragma unroll
            for (int p = 0; p < 4; p++) {
                uint32_t nrow = p * 16 + bro;
                uint32_t bh[4];
                ldsm4(bh, buf + nrow * GP + bcol);
                mmaf32(s[2 * p],     qh[ks], &bh[0]);
                mmaf32(s[2 * p + 1], qh[ks], &bh[2]);
            }
        }

        #pragma unroll
        for (int nt = 0; nt < 8; nt++) {
            s[nt][0] = exp2f(s[nt][0]);
            s[nt][1] = exp2f(s[nt][1]);
            s[nt][2] = exp2f(s[nt][2]);
            s[nt][3] = exp2f(s[nt][3]);
            l0 += s[nt][0] + s[nt][1];
            l1 += s[nt][2] + s[nt][3];
        }

        uint32_t vro = (((lane >> 3) & 1) << 3) + (lane & 7);
        uint32_t vco = (lane >> 4) << 4;
        #pragma unroll
        for (int st = 0; st < 4; st++) {
            uint32_t a_h[4];
            a_h[0] = h2pack(s[2 * st][0], s[2 * st][1]);
            a_h[1] = h2pack(s[2 * st][2], s[2 * st][3]);
            a_h[2] = h2pack(s[2 * st + 1][0], s[2 * st + 1][1]);
            a_h[3] = h2pack(s[2 * st + 1][2], s[2 * st + 1][3]);
            uint32_t jrow = st * 16 + vro;
            #pragma unroll
            for (int dp = 0; dp < 4; dp++) {
                uint32_t db = dp * 32 + vco;
                uint32_t vh[4];
                ldsm4t(vh, buf + AST + jrow * GP + db);
                mmaf32(o[2 * dp],     a_h, &vh[0]);
                mmaf32(o[2 * dp + 1], a_h, &vh[2]);
            }
        }
        __syncthreads();
    }

    l0 += __shfl_xor_sync(~0u, l0, 1); l0 += __shfl_xor_sync(~0u, l0, 2);
    l1 += __shfl_xor_sync(~0u, l1, 1); l1 += __shfl_xor_sync(~0u, l1, 2);
    float i0v = 1.f / l0, i1v = 1.f / l1;

    int g = lane >> 2, t4 = lane & 3;
    size_t ga0 = base + (size_t)(iBase + wd * 16 + g) * DIM + t4 * 2;
    size_t ga1 = ga0 + 8 * DIM;
    #pragma unroll
    for (int dt = 0; dt < 8; dt++) {
        *(uint32_t*)&Oh[ga0 + dt * 8] = h2pack(o[dt][0] * i0v, o[dt][1] * i0v);
        *(uint32_t*)&Oh[ga1 + dt * 8] = h2pack(o[dt][2] * i1v, o[dt][3] * i1v);
    }
}

// ================= launch =================
extern "C" void kernel_launch(void* const* d_in, const int* in_sizes, int n_in,
                              void* d_out, int out_size) {
    const float* x     = (const float*)d_in[0];
    const float* ln_w  = (const float*)d_in[1];
    const float* ln_b  = (const float*)d_in[2];
    const float* wq    = (const float*)d_in[3];
    const float* wk    = (const float*)d_in[4];
    const float* wv_v  = (const float*)d_in[5];
    const float* wv_g  = (const float*)d_in[6];
    const float* w_out = (const float*)d_in[7];
    float* out = (float*)d_out;

    __half *xnh, *ath, *qh, *kh, *vh;
    __half *wqh, *wkh, *wvh, *woh;
    cudaGetSymbolAddress((void**)&xnh, g_xnh);
    cudaGetSymbolAddress((void**)&ath, g_ath);
    cudaGetSymbolAddress((void**)&qh, g_qh);
    cudaGetSymbolAddress((void**)&kh, g_kh);
    cudaGetSymbolAddress((void**)&vh, g_vh);
    cudaGetSymbolAddress((void**)&wqh, g_wqh);
    cudaGetSymbolAddress((void**)&wkh, g_wkh);
    cudaGetSymbolAddress((void**)&wvh, g_wvh);
    cudaGetSymbolAddress((void**)&woh, g_woh);

    cudaFuncSetAttribute(gemm1<0>, cudaFuncAttributeMaxDynamicSharedMemorySize, G1_SMEM);
    cudaFuncSetAttribute(gemm1<1>, cudaFuncAttributeMaxDynamicSharedMemorySize, G1_SMEM);
    cudaFuncSetAttribute(attn_mma, cudaFuncAttributeMaxDynamicSharedMemorySize, A_SMEM);

    const float QSCALE = 0.125f * 1.44269504088896f;  // (1/8) * log2(e)

    prep_kernel<<<ROWS + DIM * DIM / 256 + DIM, 256>>>(x, ln_w, ln_b, wq, wk, w_out, wv_v, wv_g);

    dim3 gqkv(DIM / 128, ROWS / 128, 3);
    gemm1<0><<<gqkv, 256, G1_SMEM>>>(xnh,
                                     wqh, qh, QSCALE,
                                     wkh, kh, 1.0f,
                                     wvh, vh, 1.0f, nullptr);

    attn_mma<<<dim3(32, 16), 256, A_SMEM>>>(qh, kh, vh, ath);

    dim3 go(DIM / 128, ROWS / 128, 1);
    gemm1<1><<<go, 256, G1_SMEM>>>(ath,
                                   woh, nullptr, 1.0f,
                                   woh, nullptr, 1.0f,
                                   woh, nullptr, 1.0f, out);
}